// round 1
// baseline (speedup 1.0000x reference)
#include <cuda_runtime.h>
#include <cuda_bf16.h>

#define NN 50000
#define DD 128

// Scratch (no allocation allowed): support buffer and hidden-layer buffer.
__device__ float g_sup[(size_t)NN * DD];
__device__ float g_h[(size_t)NN * DD];

// ---------------------------------------------------------------------------
// GEMM: out[m][n] = sum_k act(X[m][k]) * W[k][n]
// BM=64, BN=128 (full width), BK=32, 256 threads, each thread 8x4 outputs.
// ---------------------------------------------------------------------------
template <bool RELU>
__global__ __launch_bounds__(256) void gemm_kernel(
    const float* __restrict__ X, const float* __restrict__ W,
    float* __restrict__ out)
{
    __shared__ float As[64][33];   // padded: column reads are broadcast anyway
    __shared__ float Bs[32][128];

    const int block_row = blockIdx.x * 64;
    const int tx = threadIdx.x & 31;  // col group: cols [tx*4, tx*4+4)
    const int ty = threadIdx.x >> 5;  // row group: rows [ty*8, ty*8+8)

    float4 acc[8];
#pragma unroll
    for (int i = 0; i < 8; i++) acc[i] = make_float4(0.f, 0.f, 0.f, 0.f);

    for (int k0 = 0; k0 < DD; k0 += 32) {
        // Load A tile: 64 rows x 32 cols = 512 float4, 2 per thread.
#pragma unroll
        for (int i = 0; i < 2; i++) {
            int idx = threadIdx.x * 2 + i;          // float4 index
            int r = idx >> 3;                       // row in tile
            int c = (idx & 7) * 4;                  // col in tile
            int gr = block_row + r;
            float4 v = make_float4(0.f, 0.f, 0.f, 0.f);
            if (gr < NN) v = *(const float4*)(X + (size_t)gr * DD + k0 + c);
            if (RELU) {
                v.x = fmaxf(v.x, 0.f); v.y = fmaxf(v.y, 0.f);
                v.z = fmaxf(v.z, 0.f); v.w = fmaxf(v.w, 0.f);
            }
            As[r][c + 0] = v.x; As[r][c + 1] = v.y;
            As[r][c + 2] = v.z; As[r][c + 3] = v.w;
        }
        // Load B tile: 32 rows x 128 cols = 1024 float4, 4 per thread.
#pragma unroll
        for (int i = 0; i < 4; i++) {
            int idx = threadIdx.x + i * 256;        // float4 index
            int r = idx >> 5;
            int c = (idx & 31) * 4;
            *(float4*)&Bs[r][c] = *(const float4*)(W + (size_t)(k0 + r) * DD + c);
        }
        __syncthreads();

#pragma unroll
        for (int kk = 0; kk < 32; kk++) {
            float4 b = *(float4*)&Bs[kk][tx * 4];
#pragma unroll
            for (int i = 0; i < 8; i++) {
                float a = As[ty * 8 + i][kk];
                acc[i].x += a * b.x;
                acc[i].y += a * b.y;
                acc[i].z += a * b.z;
                acc[i].w += a * b.w;
            }
        }
        __syncthreads();
    }

#pragma unroll
    for (int i = 0; i < 8; i++) {
        int gr = block_row + ty * 8 + i;
        if (gr < NN) *(float4*)(out + (size_t)gr * DD + tx * 4) = acc[i];
    }
}

// ---------------------------------------------------------------------------
// Init destination rows to broadcast bias: out[i][j] = b[j]
// ---------------------------------------------------------------------------
__global__ void init_bias_kernel(float* __restrict__ out, const float* __restrict__ b)
{
    int i = blockIdx.x * blockDim.x + threadIdx.x;
    if (i < NN * DD) out[i] = b[i & (DD - 1)];
}

// ---------------------------------------------------------------------------
// Scatter: warp per edge. Each lane handles one float4 (4 of 128 features).
// out[dst] += w * sup[src]
// ---------------------------------------------------------------------------
__global__ __launch_bounds__(256) void scatter_kernel(
    const float* __restrict__ sup,
    const int* __restrict__ src, const int* __restrict__ dst,
    const float* __restrict__ w, float* __restrict__ out, int nE)
{
    int e = (int)((blockIdx.x * (unsigned)blockDim.x + threadIdx.x) >> 5);
    int lane = threadIdx.x & 31;
    if (e >= nE) return;

    int s = __ldg(src + e);
    int d = __ldg(dst + e);
    float wt = __ldg(w + e);

    float4 v = *(const float4*)(sup + (size_t)s * DD + lane * 4);
    v.x *= wt; v.y *= wt; v.z *= wt; v.w *= wt;

    atomicAdd((float4*)(out + (size_t)d * DD + lane * 4), v);
}

// ---------------------------------------------------------------------------
// kernel_launch
// Inputs: 0 features[N,D] f32, 1 edge_src[E] i32, 2 edge_dst[E] i32,
//         3 edge_weight[E] f32, 4 W1[D,D] f32, 5 b1[D] f32,
//         6 W2[D,D] f32, 7 b2[D] f32
// Output: [N, D] f32
// ---------------------------------------------------------------------------
extern "C" void kernel_launch(void* const* d_in, const int* in_sizes, int n_in,
                              void* d_out, int out_size)
{
    const float* features = (const float*)d_in[0];
    const int*   edge_src = (const int*)d_in[1];
    const int*   edge_dst = (const int*)d_in[2];
    const float* edge_w   = (const float*)d_in[3];
    const float* W1       = (const float*)d_in[4];
    const float* b1       = (const float*)d_in[5];
    const float* W2       = (const float*)d_in[6];
    const float* b2       = (const float*)d_in[7];
    float* out = (float*)d_out;

    const int nE = in_sizes[1];

    float* sup; cudaGetSymbolAddress((void**)&sup, g_sup);
    float* h;   cudaGetSymbolAddress((void**)&h, g_h);

    const int gemm_grid = (NN + 63) / 64;
    const int init_grid = (NN * DD + 255) / 256;
    const long long scatter_threads = (long long)nE * 32;
    const int scatter_grid = (int)((scatter_threads + 255) / 256);

    // Layer 1: h = segsum(w * (X@W1)[src] -> dst) + b1
    init_bias_kernel<<<init_grid, 256>>>(h, b1);
    gemm_kernel<false><<<gemm_grid, 256>>>(features, W1, sup);
    scatter_kernel<<<scatter_grid, 256>>>(sup, edge_src, edge_dst, edge_w, h, nE);

    // Layer 2: out = segsum(w * (relu(h)@W2)[src] -> dst) + b2
    init_bias_kernel<<<init_grid, 256>>>(out, b2);
    gemm_kernel<true><<<gemm_grid, 256>>>(h, W2, sup);
    scatter_kernel<<<scatter_grid, 256>>>(sup, edge_src, edge_dst, edge_w, out, nE);
}

// round 2
// speedup vs baseline: 1.0419x; 1.0419x over previous
#include <cuda_runtime.h>
#include <cuda_bf16.h>

#define NN 50000
#define DD 128
#define EMAX 1600000

// Scratch (no allocation allowed)
__device__ float g_sup[(size_t)NN * DD];
__device__ float g_h[(size_t)NN * DD];
__device__ int   g_counts[NN];
__device__ int   g_offsets[NN + 1];
__device__ int   g_src_sorted[EMAX];
__device__ float g_w_sorted[EMAX];

// ---------------------------------------------------------------------------
// GEMM: out[m][n] = sum_k act(X[m][k]) * W[k][n]
// BM=64, BN=128, BK=32, 256 threads, each thread 8x4 outputs.
// ---------------------------------------------------------------------------
template <bool RELU>
__global__ __launch_bounds__(256) void gemm_kernel(
    const float* __restrict__ X, const float* __restrict__ W,
    float* __restrict__ out)
{
    __shared__ float As[64][33];
    __shared__ float Bs[32][128];

    const int block_row = blockIdx.x * 64;
    const int tx = threadIdx.x & 31;
    const int ty = threadIdx.x >> 5;

    float4 acc[8];
#pragma unroll
    for (int i = 0; i < 8; i++) acc[i] = make_float4(0.f, 0.f, 0.f, 0.f);

    for (int k0 = 0; k0 < DD; k0 += 32) {
#pragma unroll
        for (int i = 0; i < 2; i++) {
            int idx = threadIdx.x * 2 + i;
            int r = idx >> 3;
            int c = (idx & 7) * 4;
            int gr = block_row + r;
            float4 v = make_float4(0.f, 0.f, 0.f, 0.f);
            if (gr < NN) v = *(const float4*)(X + (size_t)gr * DD + k0 + c);
            if (RELU) {
                v.x = fmaxf(v.x, 0.f); v.y = fmaxf(v.y, 0.f);
                v.z = fmaxf(v.z, 0.f); v.w = fmaxf(v.w, 0.f);
            }
            As[r][c + 0] = v.x; As[r][c + 1] = v.y;
            As[r][c + 2] = v.z; As[r][c + 3] = v.w;
        }
#pragma unroll
        for (int i = 0; i < 4; i++) {
            int idx = threadIdx.x + i * 256;
            int r = idx >> 5;
            int c = (idx & 31) * 4;
            *(float4*)&Bs[r][c] = *(const float4*)(W + (size_t)(k0 + r) * DD + c);
        }
        __syncthreads();

#pragma unroll
        for (int kk = 0; kk < 32; kk++) {
            float4 b = *(float4*)&Bs[kk][tx * 4];
#pragma unroll
            for (int i = 0; i < 8; i++) {
                float a = As[ty * 8 + i][kk];
                acc[i].x += a * b.x;
                acc[i].y += a * b.y;
                acc[i].z += a * b.z;
                acc[i].w += a * b.w;
            }
        }
        __syncthreads();
    }

#pragma unroll
    for (int i = 0; i < 8; i++) {
        int gr = block_row + ty * 8 + i;
        if (gr < NN) *(float4*)(out + (size_t)gr * DD + tx * 4) = acc[i];
    }
}

// ---------------------------------------------------------------------------
// CSR build: zero -> histogram -> scan (zeroes counts) -> fill
// ---------------------------------------------------------------------------
__global__ void zero_counts_kernel(int* __restrict__ counts)
{
    int i = blockIdx.x * blockDim.x + threadIdx.x;
    if (i < NN) counts[i] = 0;
}

__global__ void hist_kernel(const int* __restrict__ dst, int* __restrict__ counts, int nE)
{
    int e = blockIdx.x * blockDim.x + threadIdx.x;
    if (e < nE) atomicAdd(counts + __ldg(dst + e), 1);
}

// Single block of 1024 threads: exclusive scan of counts into offsets[1..NN],
// offsets[0]=0. Also zeroes counts (used as cursor by fill).
__global__ __launch_bounds__(1024) void scan_kernel(
    int* __restrict__ counts, int* __restrict__ offsets)
{
    __shared__ int sh[1024];
    const int tid = threadIdx.x;
    if (tid == 0) offsets[0] = 0;
    int carry = 0;
    for (int base = 0; base < NN; base += 1024) {
        int i = base + tid;
        int v = 0;
        if (i < NN) { v = counts[i]; counts[i] = 0; }
        sh[tid] = v;
        __syncthreads();
#pragma unroll
        for (int off = 1; off < 1024; off <<= 1) {
            int t = (tid >= off) ? sh[tid - off] : 0;
            __syncthreads();
            sh[tid] += t;
            __syncthreads();
        }
        if (i < NN) offsets[i + 1] = carry + sh[tid];
        carry += sh[1023];
        __syncthreads();
    }
}

__global__ void fill_kernel(
    const int* __restrict__ src, const int* __restrict__ dst,
    const float* __restrict__ w,
    const int* __restrict__ offsets, int* __restrict__ cursor,
    int* __restrict__ src_sorted, float* __restrict__ w_sorted, int nE)
{
    int e = blockIdx.x * blockDim.x + threadIdx.x;
    if (e >= nE) return;
    int d = __ldg(dst + e);
    int pos = __ldg(offsets + d) + atomicAdd(cursor + d, 1);
    src_sorted[pos] = __ldg(src + e);
    w_sorted[pos] = __ldg(w + e);
}

// ---------------------------------------------------------------------------
// Gather-aggregate: warp per node. out[n] = bias + sum_{e in CSR[n]} w_e * sup[src_e]
// ---------------------------------------------------------------------------
__global__ __launch_bounds__(256) void gather_kernel(
    const float* __restrict__ sup,
    const int* __restrict__ src_sorted, const float* __restrict__ w_sorted,
    const int* __restrict__ offsets, const float* __restrict__ bias,
    float* __restrict__ out)
{
    int n = (int)((blockIdx.x * (unsigned)blockDim.x + threadIdx.x) >> 5);
    int lane = threadIdx.x & 31;
    if (n >= NN) return;

    int beg = __ldg(offsets + n);
    int end = __ldg(offsets + n + 1);

    float4 acc = *(const float4*)(bias + lane * 4);

    int j = beg;
    // software-pipelined by 2 for MLP
    for (; j + 1 < end; j += 2) {
        int s0 = __ldg(src_sorted + j);
        int s1 = __ldg(src_sorted + j + 1);
        float w0 = __ldg(w_sorted + j);
        float w1 = __ldg(w_sorted + j + 1);
        float4 v0 = *(const float4*)(sup + (size_t)s0 * DD + lane * 4);
        float4 v1 = *(const float4*)(sup + (size_t)s1 * DD + lane * 4);
        acc.x += w0 * v0.x; acc.y += w0 * v0.y;
        acc.z += w0 * v0.z; acc.w += w0 * v0.w;
        acc.x += w1 * v1.x; acc.y += w1 * v1.y;
        acc.z += w1 * v1.z; acc.w += w1 * v1.w;
    }
    if (j < end) {
        int s0 = __ldg(src_sorted + j);
        float w0 = __ldg(w_sorted + j);
        float4 v0 = *(const float4*)(sup + (size_t)s0 * DD + lane * 4);
        acc.x += w0 * v0.x; acc.y += w0 * v0.y;
        acc.z += w0 * v0.z; acc.w += w0 * v0.w;
    }

    *(float4*)(out + (size_t)n * DD + lane * 4) = acc;
}

// ---------------------------------------------------------------------------
// kernel_launch
// ---------------------------------------------------------------------------
extern "C" void kernel_launch(void* const* d_in, const int* in_sizes, int n_in,
                              void* d_out, int out_size)
{
    const float* features = (const float*)d_in[0];
    const int*   edge_src = (const int*)d_in[1];
    const int*   edge_dst = (const int*)d_in[2];
    const float* edge_w   = (const float*)d_in[3];
    const float* W1       = (const float*)d_in[4];
    const float* b1       = (const float*)d_in[5];
    const float* W2       = (const float*)d_in[6];
    const float* b2       = (const float*)d_in[7];
    float* out = (float*)d_out;

    const int nE = in_sizes[1];

    float* sup;     cudaGetSymbolAddress((void**)&sup, g_sup);
    float* h;       cudaGetSymbolAddress((void**)&h, g_h);
    int* counts;    cudaGetSymbolAddress((void**)&counts, g_counts);
    int* offsets;   cudaGetSymbolAddress((void**)&offsets, g_offsets);
    int* srcs;      cudaGetSymbolAddress((void**)&srcs, g_src_sorted);
    float* ws;      cudaGetSymbolAddress((void**)&ws, g_w_sorted);

    const int gemm_grid = (NN + 63) / 64;
    const int edge_grid = (nE + 255) / 256;
    const int node_grid = (NN + 255) / 256;
    const int gather_grid = (NN * 32 + 255) / 256;

    // ---- CSR build (per-replay; deterministic given inputs) ----
    zero_counts_kernel<<<node_grid, 256>>>(counts);
    hist_kernel<<<edge_grid, 256>>>(edge_dst, counts, nE);
    scan_kernel<<<1, 1024>>>(counts, offsets);
    fill_kernel<<<edge_grid, 256>>>(edge_src, edge_dst, edge_w,
                                    offsets, counts, srcs, ws, nE);

    // ---- Layer 1: h = bias1 + gather(w * (X@W1)[src]) ----
    gemm_kernel<false><<<gemm_grid, 256>>>(features, W1, sup);
    gather_kernel<<<gather_grid, 256>>>(sup, srcs, ws, offsets, b1, h);

    // ---- Layer 2: out = bias2 + gather(w * (relu(h)@W2)[src]) ----
    gemm_kernel<true><<<gemm_grid, 256>>>(h, W2, sup);
    gather_kernel<<<gather_grid, 256>>>(sup, srcs, ws, offsets, b2, out);
}

// round 3
// speedup vs baseline: 1.7134x; 1.6446x over previous
#include <cuda_runtime.h>
#include <cuda_bf16.h>

#define NN 50000
#define DD 128
#define EMAX 1600000

// Scratch (no allocation allowed)
__device__ float g_sup[(size_t)NN * DD];
__device__ float g_h[(size_t)NN * DD];
__device__ int   g_counts[NN];
__device__ int   g_offsets[NN + 1];
__device__ int2  g_edges[EMAX];   // packed (src, weight-as-int)

// ---------------------------------------------------------------------------
// GEMM: out[m][n] = sum_k act(X[m][k]) * W[k][n]
// BM=64, BN=128, BK=32, 256 threads, each thread 8x4 outputs.
// ---------------------------------------------------------------------------
template <bool RELU>
__global__ __launch_bounds__(256) void gemm_kernel(
    const float* __restrict__ X, const float* __restrict__ W,
    float* __restrict__ out)
{
    __shared__ float As[64][33];
    __shared__ float Bs[32][128];

    const int block_row = blockIdx.x * 64;
    const int tx = threadIdx.x & 31;
    const int ty = threadIdx.x >> 5;

    float4 acc[8];
#pragma unroll
    for (int i = 0; i < 8; i++) acc[i] = make_float4(0.f, 0.f, 0.f, 0.f);

    for (int k0 = 0; k0 < DD; k0 += 32) {
#pragma unroll
        for (int i = 0; i < 2; i++) {
            int idx = threadIdx.x * 2 + i;
            int r = idx >> 3;
            int c = (idx & 7) * 4;
            int gr = block_row + r;
            float4 v = make_float4(0.f, 0.f, 0.f, 0.f);
            if (gr < NN) v = *(const float4*)(X + (size_t)gr * DD + k0 + c);
            if (RELU) {
                v.x = fmaxf(v.x, 0.f); v.y = fmaxf(v.y, 0.f);
                v.z = fmaxf(v.z, 0.f); v.w = fmaxf(v.w, 0.f);
            }
            As[r][c + 0] = v.x; As[r][c + 1] = v.y;
            As[r][c + 2] = v.z; As[r][c + 3] = v.w;
        }
#pragma unroll
        for (int i = 0; i < 4; i++) {
            int idx = threadIdx.x + i * 256;
            int r = idx >> 5;
            int c = (idx & 31) * 4;
            *(float4*)&Bs[r][c] = *(const float4*)(W + (size_t)(k0 + r) * DD + c);
        }
        __syncthreads();

#pragma unroll
        for (int kk = 0; kk < 32; kk++) {
            float4 b = *(float4*)&Bs[kk][tx * 4];
#pragma unroll
            for (int i = 0; i < 8; i++) {
                float a = As[ty * 8 + i][kk];
                acc[i].x += a * b.x;
                acc[i].y += a * b.y;
                acc[i].z += a * b.z;
                acc[i].w += a * b.w;
            }
        }
        __syncthreads();
    }

#pragma unroll
    for (int i = 0; i < 8; i++) {
        int gr = block_row + ty * 8 + i;
        if (gr < NN) *(float4*)(out + (size_t)gr * DD + tx * 4) = acc[i];
    }
}

// ---------------------------------------------------------------------------
// CSR build
// ---------------------------------------------------------------------------
__global__ void zero_counts_kernel(int* __restrict__ counts)
{
    int i = blockIdx.x * blockDim.x + threadIdx.x;
    if (i < NN) counts[i] = 0;
}

__global__ void hist_kernel(const int* __restrict__ dst, int* __restrict__ counts, int nE)
{
    int e = blockIdx.x * blockDim.x + threadIdx.x;
    if (e < nE) atomicAdd(counts + __ldg(dst + e), 1);
}

// Single block, 1024 threads, warp-shuffle scan. Exclusive scan of counts into
// offsets[1..NN]; offsets[0]=0. Zeroes counts (reused as cursor by fill).
__global__ __launch_bounds__(1024) void scan_kernel(
    int* __restrict__ counts, int* __restrict__ offsets)
{
    __shared__ int warp_sums[32];
    const int tid = threadIdx.x;
    const int lane = tid & 31;
    const int wid = tid >> 5;
    if (tid == 0) offsets[0] = 0;

    int carry = 0;
    for (int base = 0; base < NN; base += 1024) {
        int i = base + tid;
        int v = 0;
        if (i < NN) { v = counts[i]; counts[i] = 0; }

        // warp inclusive scan
#pragma unroll
        for (int off = 1; off < 32; off <<= 1) {
            int t = __shfl_up_sync(0xffffffffu, v, off);
            if (lane >= off) v += t;
        }
        if (lane == 31) warp_sums[wid] = v;
        __syncthreads();
        if (wid == 0) {
            int s = warp_sums[lane];
#pragma unroll
            for (int off = 1; off < 32; off <<= 1) {
                int t = __shfl_up_sync(0xffffffffu, s, off);
                if (lane >= off) s += t;
            }
            warp_sums[lane] = s;
        }
        __syncthreads();
        int add = (wid > 0) ? warp_sums[wid - 1] : 0;
        if (i < NN) offsets[i + 1] = carry + add + v;
        int total = warp_sums[31];
        __syncthreads();   // everyone done reading before next tile overwrites
        carry += total;
    }
}

__global__ void fill_kernel(
    const int* __restrict__ src, const int* __restrict__ dst,
    const float* __restrict__ w,
    const int* __restrict__ offsets, int* __restrict__ cursor,
    int2* __restrict__ edges, int nE)
{
    int e = blockIdx.x * blockDim.x + threadIdx.x;
    if (e >= nE) return;
    int d = __ldg(dst + e);
    int pos = __ldg(offsets + d) + atomicAdd(cursor + d, 1);
    edges[pos] = make_int2(__ldg(src + e), __float_as_int(__ldg(w + e)));
}

// ---------------------------------------------------------------------------
// Gather-aggregate: warp per node.
// out[n] = bias + sum_{e in CSR[n]} w_e * sup[src_e]
// Cooperative index preload (1 int2 per lane) -> shfl broadcast -> batched
// independent row loads (unroll 8) for high MLP.
// ---------------------------------------------------------------------------
__global__ __launch_bounds__(256) void gather_kernel(
    const float* __restrict__ sup,
    const int2* __restrict__ edges,
    const int* __restrict__ offsets, const float* __restrict__ bias,
    float* __restrict__ out)
{
    int n = (int)((blockIdx.x * (unsigned)blockDim.x + threadIdx.x) >> 5);
    int lane = threadIdx.x & 31;
    if (n >= NN) return;

    int beg = __ldg(offsets + n);
    int end = __ldg(offsets + n + 1);

    float4 acc = *(const float4*)(bias + lane * 4);

    for (int base = beg; base < end; base += 32) {
        int cnt = min(32, end - base);
        int2 p = make_int2(0, 0);
        if (lane < cnt) p = __ldg(edges + base + lane);

        int k = 0;
        for (; k + 8 <= cnt; k += 8) {
            const float* r[8];
            float wgt[8];
#pragma unroll
            for (int u = 0; u < 8; u++) {
                int s = __shfl_sync(0xffffffffu, p.x, k + u);
                wgt[u] = __int_as_float(__shfl_sync(0xffffffffu, p.y, k + u));
                r[u] = sup + (size_t)s * DD + lane * 4;
            }
            float4 v[8];
#pragma unroll
            for (int u = 0; u < 8; u++) v[u] = *(const float4*)r[u];
#pragma unroll
            for (int u = 0; u < 8; u++) {
                acc.x += wgt[u] * v[u].x;
                acc.y += wgt[u] * v[u].y;
                acc.z += wgt[u] * v[u].z;
                acc.w += wgt[u] * v[u].w;
            }
        }
        for (; k < cnt; k++) {
            int s = __shfl_sync(0xffffffffu, p.x, k);
            float wg = __int_as_float(__shfl_sync(0xffffffffu, p.y, k));
            float4 v = *(const float4*)(sup + (size_t)s * DD + lane * 4);
            acc.x += wg * v.x; acc.y += wg * v.y;
            acc.z += wg * v.z; acc.w += wg * v.w;
        }
    }

    *(float4*)(out + (size_t)n * DD + lane * 4) = acc;
}

// ---------------------------------------------------------------------------
// kernel_launch
// ---------------------------------------------------------------------------
extern "C" void kernel_launch(void* const* d_in, const int* in_sizes, int n_in,
                              void* d_out, int out_size)
{
    const float* features = (const float*)d_in[0];
    const int*   edge_src = (const int*)d_in[1];
    const int*   edge_dst = (const int*)d_in[2];
    const float* edge_w   = (const float*)d_in[3];
    const float* W1       = (const float*)d_in[4];
    const float* b1       = (const float*)d_in[5];
    const float* W2       = (const float*)d_in[6];
    const float* b2       = (const float*)d_in[7];
    float* out = (float*)d_out;

    const int nE = in_sizes[1];

    float* sup;     cudaGetSymbolAddress((void**)&sup, g_sup);
    float* h;       cudaGetSymbolAddress((void**)&h, g_h);
    int* counts;    cudaGetSymbolAddress((void**)&counts, g_counts);
    int* offsets;   cudaGetSymbolAddress((void**)&offsets, g_offsets);
    int2* edges;    cudaGetSymbolAddress((void**)&edges, g_edges);

    const int gemm_grid = (NN + 63) / 64;
    const int edge_grid = (nE + 255) / 256;
    const int node_grid = (NN + 255) / 256;
    const int gather_grid = (NN * 32 + 255) / 256;

    // ---- CSR build ----
    zero_counts_kernel<<<node_grid, 256>>>(counts);
    hist_kernel<<<edge_grid, 256>>>(edge_dst, counts, nE);
    scan_kernel<<<1, 1024>>>(counts, offsets);
    fill_kernel<<<edge_grid, 256>>>(edge_src, edge_dst, edge_w,
                                    offsets, counts, edges, nE);

    // ---- Layer 1 ----
    gemm_kernel<false><<<gemm_grid, 256>>>(features, W1, sup);
    gather_kernel<<<gather_grid, 256>>>(sup, edges, offsets, b1, h);

    // ---- Layer 2 ----
    gemm_kernel<true><<<gemm_grid, 256>>>(h, W2, sup);
    gather_kernel<<<gather_grid, 256>>>(sup, edges, offsets, b2, out);
}

// round 4
// speedup vs baseline: 1.8798x; 1.0971x over previous
#include <cuda_runtime.h>
#include <cuda_fp16.h>
#include <cuda_bf16.h>

#define NN 50000
#define DD 128
#define EMAX 1600000

// Scratch (no allocation allowed)
__device__ __half g_sup[(size_t)NN * DD];   // support in fp16 (gather operand)
__device__ float  g_h[(size_t)NN * DD];
__device__ int    g_counts[NN];
__device__ int    g_offsets[NN + 1];
__device__ int2   g_edges[EMAX];            // packed (src, weight-as-int)

// ---------------------------------------------------------------------------
// GEMM: sup[m][n] = (half) sum_k act(X[m][k]) * W[k][n]
// BM=64, BN=128, BK=32, 256 threads, each thread 8x4 outputs. fp32 math,
// fp16 output.
// ---------------------------------------------------------------------------
template <bool RELU>
__global__ __launch_bounds__(256) void gemm_kernel(
    const float* __restrict__ X, const float* __restrict__ W,
    __half* __restrict__ out)
{
    __shared__ float As[64][33];
    __shared__ float Bs[32][128];

    const int block_row = blockIdx.x * 64;
    const int tx = threadIdx.x & 31;
    const int ty = threadIdx.x >> 5;

    float4 acc[8];
#pragma unroll
    for (int i = 0; i < 8; i++) acc[i] = make_float4(0.f, 0.f, 0.f, 0.f);

    for (int k0 = 0; k0 < DD; k0 += 32) {
#pragma unroll
        for (int i = 0; i < 2; i++) {
            int idx = threadIdx.x * 2 + i;
            int r = idx >> 3;
            int c = (idx & 7) * 4;
            int gr = block_row + r;
            float4 v = make_float4(0.f, 0.f, 0.f, 0.f);
            if (gr < NN) v = *(const float4*)(X + (size_t)gr * DD + k0 + c);
            if (RELU) {
                v.x = fmaxf(v.x, 0.f); v.y = fmaxf(v.y, 0.f);
                v.z = fmaxf(v.z, 0.f); v.w = fmaxf(v.w, 0.f);
            }
            As[r][c + 0] = v.x; As[r][c + 1] = v.y;
            As[r][c + 2] = v.z; As[r][c + 3] = v.w;
        }
#pragma unroll
        for (int i = 0; i < 4; i++) {
            int idx = threadIdx.x + i * 256;
            int r = idx >> 5;
            int c = (idx & 31) * 4;
            *(float4*)&Bs[r][c] = *(const float4*)(W + (size_t)(k0 + r) * DD + c);
        }
        __syncthreads();

#pragma unroll
        for (int kk = 0; kk < 32; kk++) {
            float4 b = *(float4*)&Bs[kk][tx * 4];
#pragma unroll
            for (int i = 0; i < 8; i++) {
                float a = As[ty * 8 + i][kk];
                acc[i].x += a * b.x;
                acc[i].y += a * b.y;
                acc[i].z += a * b.z;
                acc[i].w += a * b.w;
            }
        }
        __syncthreads();
    }

#pragma unroll
    for (int i = 0; i < 8; i++) {
        int gr = block_row + ty * 8 + i;
        if (gr < NN) {
            __half2 p0 = __floats2half2_rn(acc[i].x, acc[i].y);
            __half2 p1 = __floats2half2_rn(acc[i].z, acc[i].w);
            uint2 pk;
            pk.x = *reinterpret_cast<unsigned*>(&p0);
            pk.y = *reinterpret_cast<unsigned*>(&p1);
            *(uint2*)(out + (size_t)gr * DD + tx * 4) = pk;
        }
    }
}

// ---------------------------------------------------------------------------
// CSR build
// ---------------------------------------------------------------------------
__global__ void zero_counts_kernel(int* __restrict__ counts)
{
    int i = blockIdx.x * blockDim.x + threadIdx.x;
    if (i < NN) counts[i] = 0;
}

__global__ void hist_kernel(const int* __restrict__ dst, int* __restrict__ counts, int nE)
{
    int e = blockIdx.x * blockDim.x + threadIdx.x;
    if (e < nE) atomicAdd(counts + __ldg(dst + e), 1);
}

// Single block, 1024 threads, warp-shuffle scan.
__global__ __launch_bounds__(1024) void scan_kernel(
    int* __restrict__ counts, int* __restrict__ offsets)
{
    __shared__ int warp_sums[32];
    const int tid = threadIdx.x;
    const int lane = tid & 31;
    const int wid = tid >> 5;
    if (tid == 0) offsets[0] = 0;

    int carry = 0;
    for (int base = 0; base < NN; base += 1024) {
        int i = base + tid;
        int v = 0;
        if (i < NN) { v = counts[i]; counts[i] = 0; }

#pragma unroll
        for (int off = 1; off < 32; off <<= 1) {
            int t = __shfl_up_sync(0xffffffffu, v, off);
            if (lane >= off) v += t;
        }
        if (lane == 31) warp_sums[wid] = v;
        __syncthreads();
        if (wid == 0) {
            int s = warp_sums[lane];
#pragma unroll
            for (int off = 1; off < 32; off <<= 1) {
                int t = __shfl_up_sync(0xffffffffu, s, off);
                if (lane >= off) s += t;
            }
            warp_sums[lane] = s;
        }
        __syncthreads();
        int add = (wid > 0) ? warp_sums[wid - 1] : 0;
        if (i < NN) offsets[i + 1] = carry + add + v;
        int total = warp_sums[31];
        __syncthreads();
        carry += total;
    }
}

__global__ void fill_kernel(
    const int* __restrict__ src, const int* __restrict__ dst,
    const float* __restrict__ w,
    const int* __restrict__ offsets, int* __restrict__ cursor,
    int2* __restrict__ edges, int nE)
{
    int e = blockIdx.x * blockDim.x + threadIdx.x;
    if (e >= nE) return;
    int d = __ldg(dst + e);
    int pos = __ldg(offsets + d) + atomicAdd(cursor + d, 1);
    edges[pos] = make_int2(__ldg(src + e), __float_as_int(__ldg(w + e)));
}

// ---------------------------------------------------------------------------
// Gather-aggregate: warp per node.  out[n] = bias + sum w_e * sup_fp16[src_e]
// fp16 rows (256 B/edge), fp32 accumulate. Index preload + shfl broadcast,
// unroll 8 for MLP.
// ---------------------------------------------------------------------------
__global__ __launch_bounds__(256) void gather_kernel(
    const __half* __restrict__ sup,
    const int2* __restrict__ edges,
    const int* __restrict__ offsets, const float* __restrict__ bias,
    float* __restrict__ out)
{
    int n = (int)((blockIdx.x * (unsigned)blockDim.x + threadIdx.x) >> 5);
    int lane = threadIdx.x & 31;
    if (n >= NN) return;

    int beg = __ldg(offsets + n);
    int end = __ldg(offsets + n + 1);

    float4 acc = *(const float4*)(bias + lane * 4);

    for (int base = beg; base < end; base += 32) {
        int cnt = min(32, end - base);
        int2 p = make_int2(0, 0);
        if (lane < cnt) p = __ldg(edges + base + lane);

        int k = 0;
        for (; k + 8 <= cnt; k += 8) {
            const __half* r[8];
            float wgt[8];
#pragma unroll
            for (int u = 0; u < 8; u++) {
                int s = __shfl_sync(0xffffffffu, p.x, k + u);
                wgt[u] = __int_as_float(__shfl_sync(0xffffffffu, p.y, k + u));
                r[u] = sup + (size_t)s * DD + lane * 4;
            }
            uint2 v[8];
#pragma unroll
            for (int u = 0; u < 8; u++) v[u] = *(const uint2*)r[u];
#pragma unroll
            for (int u = 0; u < 8; u++) {
                float2 f0 = __half22float2(*reinterpret_cast<__half2*>(&v[u].x));
                float2 f1 = __half22float2(*reinterpret_cast<__half2*>(&v[u].y));
                acc.x += wgt[u] * f0.x;
                acc.y += wgt[u] * f0.y;
                acc.z += wgt[u] * f1.x;
                acc.w += wgt[u] * f1.y;
            }
        }
        for (; k < cnt; k++) {
            int s = __shfl_sync(0xffffffffu, p.x, k);
            float wg = __int_as_float(__shfl_sync(0xffffffffu, p.y, k));
            uint2 v = *(const uint2*)(sup + (size_t)s * DD + lane * 4);
            float2 f0 = __half22float2(*reinterpret_cast<__half2*>(&v.x));
            float2 f1 = __half22float2(*reinterpret_cast<__half2*>(&v.y));
            acc.x += wg * f0.x; acc.y += wg * f0.y;
            acc.z += wg * f1.x; acc.w += wg * f1.y;
        }
    }

    *(float4*)(out + (size_t)n * DD + lane * 4) = acc;
}

// ---------------------------------------------------------------------------
// kernel_launch
// ---------------------------------------------------------------------------
extern "C" void kernel_launch(void* const* d_in, const int* in_sizes, int n_in,
                              void* d_out, int out_size)
{
    const float* features = (const float*)d_in[0];
    const int*   edge_src = (const int*)d_in[1];
    const int*   edge_dst = (const int*)d_in[2];
    const float* edge_w   = (const float*)d_in[3];
    const float* W1       = (const float*)d_in[4];
    const float* b1       = (const float*)d_in[5];
    const float* W2       = (const float*)d_in[6];
    const float* b2       = (const float*)d_in[7];
    float* out = (float*)d_out;

    const int nE = in_sizes[1];

    __half* sup;  cudaGetSymbolAddress((void**)&sup, g_sup);
    float* h;     cudaGetSymbolAddress((void**)&h, g_h);
    int* counts;  cudaGetSymbolAddress((void**)&counts, g_counts);
    int* offsets; cudaGetSymbolAddress((void**)&offsets, g_offsets);
    int2* edges;  cudaGetSymbolAddress((void**)&edges, g_edges);

    const int gemm_grid = (NN + 63) / 64;
    const int edge_grid = (nE + 255) / 256;
    const int node_grid = (NN + 255) / 256;
    const int gather_grid = (NN * 32 + 255) / 256;

    // ---- CSR build ----
    zero_counts_kernel<<<node_grid, 256>>>(counts);
    hist_kernel<<<edge_grid, 256>>>(edge_dst, counts, nE);
    scan_kernel<<<1, 1024>>>(counts, offsets);
    fill_kernel<<<edge_grid, 256>>>(edge_src, edge_dst, edge_w,
                                    offsets, counts, edges, nE);

    // ---- Layer 1 ----
    gemm_kernel<false><<<gemm_grid, 256>>>(features, W1, sup);
    gather_kernel<<<gather_grid, 256>>>(sup, edges, offsets, b1, h);

    // ---- Layer 2 ----
    gemm_kernel<true><<<gemm_grid, 256>>>(h, W2, sup);
    gather_kernel<<<gather_grid, 256>>>(sup, edges, offsets, b2, out);
}

// round 5
// speedup vs baseline: 2.4775x; 1.3180x over previous
#include <cuda_runtime.h>
#include <cuda_fp16.h>
#include <cuda_bf16.h>

#define NN 50000
#define DD 128
#define EMAX 1600000

typedef unsigned int uint;

// Scratch (no allocation allowed)
__device__ __half g_sup[(size_t)NN * DD];   // support (gather operand), fp16
__device__ __half g_h[(size_t)NN * DD];     // hidden layer, fp16
__device__ __half g_w1t[DD * DD];           // W1^T fp16 ([n][k])
__device__ __half g_w2t[DD * DD];           // W2^T fp16
__device__ int    g_counts[NN];
__device__ int    g_offsets[NN + 1];
__device__ int2   g_edges[EMAX];            // packed (src, weight-as-int)

// ---------------------------------------------------------------------------
// Convert + transpose W: Wt[n][k] = (half) W[k][n]
// ---------------------------------------------------------------------------
__global__ void convert_w_kernel(const float* __restrict__ W, __half* __restrict__ Wt)
{
    int idx = blockIdx.x * blockDim.x + threadIdx.x;
    if (idx < DD * DD) {
        int k = idx >> 7;
        int n = idx & 127;
        Wt[n * DD + k] = __float2half(W[idx]);
    }
}

// ---------------------------------------------------------------------------
// HGEMM via mma.sync m16n8k16 (fp16 in, fp32 acc, fp16 out).
// out[m][n] = sum_k act(X[m][k]) * W[k][n],  Wt given as [n][k].
// BM=64, BN=128, K=128 fully staged in smem. 256 threads = 8 warps (2Mx4N),
// each warp: m32 x n32 = 2 m-tiles x 4 n-tiles of m16n8.
// ---------------------------------------------------------------------------
#define GEMM_SMEM ((64 + 128) * 136 * 2)

template <typename InT, bool RELU>
__global__ __launch_bounds__(256) void hgemm_kernel(
    const InT* __restrict__ X, const __half* __restrict__ Wt,
    __half* __restrict__ out)
{
    extern __shared__ __align__(16) __half sh[];
    __half (*Ash)[136] = reinterpret_cast<__half(*)[136]>(sh);            // 64 x 136
    __half (*Bsh)[136] = reinterpret_cast<__half(*)[136]>(sh + 64 * 136); // 128 x 136

    const int tid = threadIdx.x;
    const int lane = tid & 31;
    const int wid = tid >> 5;
    const int block_row = blockIdx.x * 64;

    // ---- Load B: Wt [128][128] -> Bsh[n][k] ----
#pragma unroll
    for (int i = 0; i < 16; i++) {
        int idx = tid + i * 256;            // uint2 units (4 halfs)
        int n = idx >> 5;
        int c4 = (idx & 31) * 4;
        uint2 v = *(const uint2*)(Wt + n * DD + c4);
        *(uint2*)&Bsh[n][c4] = v;
    }

    // ---- Load A tile: 64 x 128, convert/relu -> Ash ----
    if constexpr (sizeof(InT) == 4) {
#pragma unroll
        for (int i = 0; i < 8; i++) {
            int idx = tid + i * 256;        // float4 units
            int r = idx >> 5;
            int c4 = (idx & 31) * 4;
            int gr = block_row + r;
            float4 v = make_float4(0.f, 0.f, 0.f, 0.f);
            if (gr < NN) v = *(const float4*)((const float*)X + (size_t)gr * DD + c4);
            if (RELU) {
                v.x = fmaxf(v.x, 0.f); v.y = fmaxf(v.y, 0.f);
                v.z = fmaxf(v.z, 0.f); v.w = fmaxf(v.w, 0.f);
            }
            __half2 h0 = __floats2half2_rn(v.x, v.y);
            __half2 h1 = __floats2half2_rn(v.z, v.w);
            uint2 pk;
            pk.x = *reinterpret_cast<uint*>(&h0);
            pk.y = *reinterpret_cast<uint*>(&h1);
            *(uint2*)&Ash[r][c4] = pk;
        }
    } else {
#pragma unroll
        for (int i = 0; i < 8; i++) {
            int idx = tid + i * 256;        // uint2 units (4 halfs)
            int r = idx >> 5;
            int c4 = (idx & 31) * 4;
            int gr = block_row + r;
            uint2 v = make_uint2(0u, 0u);
            if (gr < NN) v = *(const uint2*)((const __half*)X + (size_t)gr * DD + c4);
            if (RELU) {
                __half2 z = __float2half2_rn(0.f);
                __half2 a = __hmax2(*reinterpret_cast<__half2*>(&v.x), z);
                __half2 b = __hmax2(*reinterpret_cast<__half2*>(&v.y), z);
                v.x = *reinterpret_cast<uint*>(&a);
                v.y = *reinterpret_cast<uint*>(&b);
            }
            *(uint2*)&Ash[r][c4] = v;
        }
    }
    __syncthreads();

    // ---- Compute ----
    const int warp_m = (wid >> 2) * 32;   // 0 or 32
    const int warp_n = (wid & 3) * 32;    // 0,32,64,96
    const int gr = lane >> 2;             // group row / B col
    const int qc = lane & 3;              // quad id

    float acc[2][4][4];
#pragma unroll
    for (int mt = 0; mt < 2; mt++)
#pragma unroll
        for (int nt = 0; nt < 4; nt++)
#pragma unroll
            for (int j = 0; j < 4; j++) acc[mt][nt][j] = 0.f;

#pragma unroll
    for (int k0 = 0; k0 < DD; k0 += 16) {
        int kc = k0 + 2 * qc;
        uint a[2][4];
#pragma unroll
        for (int mt = 0; mt < 2; mt++) {
            int r0 = warp_m + mt * 16 + gr;
            a[mt][0] = *(const uint*)&Ash[r0][kc];
            a[mt][1] = *(const uint*)&Ash[r0 + 8][kc];
            a[mt][2] = *(const uint*)&Ash[r0][kc + 8];
            a[mt][3] = *(const uint*)&Ash[r0 + 8][kc + 8];
        }
#pragma unroll
        for (int nt = 0; nt < 4; nt++) {
            int n = warp_n + nt * 8 + gr;
            uint b0 = *(const uint*)&Bsh[n][kc];
            uint b1 = *(const uint*)&Bsh[n][kc + 8];
#pragma unroll
            for (int mt = 0; mt < 2; mt++) {
                asm volatile(
                    "mma.sync.aligned.m16n8k16.row.col.f32.f16.f16.f32 "
                    "{%0,%1,%2,%3}, {%4,%5,%6,%7}, {%8,%9}, {%0,%1,%2,%3};"
                    : "+f"(acc[mt][nt][0]), "+f"(acc[mt][nt][1]),
                      "+f"(acc[mt][nt][2]), "+f"(acc[mt][nt][3])
                    : "r"(a[mt][0]), "r"(a[mt][1]), "r"(a[mt][2]), "r"(a[mt][3]),
                      "r"(b0), "r"(b1));
            }
        }
    }

    // ---- Store (fp16) ----
#pragma unroll
    for (int mt = 0; mt < 2; mt++) {
        int r0 = block_row + warp_m + mt * 16 + gr;
#pragma unroll
        for (int nt = 0; nt < 4; nt++) {
            int col = warp_n + nt * 8 + 2 * qc;
            if (r0 < NN) {
                __half2 p = __floats2half2_rn(acc[mt][nt][0], acc[mt][nt][1]);
                *(__half2*)(out + (size_t)r0 * DD + col) = p;
            }
            if (r0 + 8 < NN) {
                __half2 p = __floats2half2_rn(acc[mt][nt][2], acc[mt][nt][3]);
                *(__half2*)(out + (size_t)(r0 + 8) * DD + col) = p;
            }
        }
    }
}

// ---------------------------------------------------------------------------
// CSR build
// ---------------------------------------------------------------------------
__global__ void zero_counts_kernel(int* __restrict__ counts)
{
    int i = blockIdx.x * blockDim.x + threadIdx.x;
    if (i < NN) counts[i] = 0;
}

__global__ void hist_kernel(const int* __restrict__ dst, int* __restrict__ counts, int nE)
{
    int base = blockIdx.x * blockDim.x * 4 + threadIdx.x;
    int d[4];
#pragma unroll
    for (int i = 0; i < 4; i++) {
        int e = base + i * blockDim.x;
        d[i] = (e < nE) ? __ldg(dst + e) : -1;
    }
#pragma unroll
    for (int i = 0; i < 4; i++)
        if (d[i] >= 0) atomicAdd(counts + d[i], 1);
}

// Single block, 1024 threads, warp-shuffle scan.
__global__ __launch_bounds__(1024) void scan_kernel(
    int* __restrict__ counts, int* __restrict__ offsets)
{
    __shared__ int warp_sums[32];
    const int tid = threadIdx.x;
    const int lane = tid & 31;
    const int wid = tid >> 5;
    if (tid == 0) offsets[0] = 0;

    int carry = 0;
    for (int base = 0; base < NN; base += 1024) {
        int i = base + tid;
        int v = 0;
        if (i < NN) { v = counts[i]; counts[i] = 0; }

#pragma unroll
        for (int off = 1; off < 32; off <<= 1) {
            int t = __shfl_up_sync(0xffffffffu, v, off);
            if (lane >= off) v += t;
        }
        if (lane == 31) warp_sums[wid] = v;
        __syncthreads();
        if (wid == 0) {
            int s = warp_sums[lane];
#pragma unroll
            for (int off = 1; off < 32; off <<= 1) {
                int t = __shfl_up_sync(0xffffffffu, s, off);
                if (lane >= off) s += t;
            }
            warp_sums[lane] = s;
        }
        __syncthreads();
        int add = (wid > 0) ? warp_sums[wid - 1] : 0;
        if (i < NN) offsets[i + 1] = carry + add + v;
        int total = warp_sums[31];
        __syncthreads();
        carry += total;
    }
}

__global__ void fill_kernel(
    const int* __restrict__ src, const int* __restrict__ dst,
    const float* __restrict__ w,
    const int* __restrict__ offsets, int* __restrict__ cursor,
    int2* __restrict__ edges, int nE)
{
    int base = blockIdx.x * blockDim.x * 4 + threadIdx.x;
    int d[4], s[4];
    float wt[4];
#pragma unroll
    for (int i = 0; i < 4; i++) {
        int e = base + i * blockDim.x;
        if (e < nE) {
            d[i] = __ldg(dst + e);
            s[i] = __ldg(src + e);
            wt[i] = __ldg(w + e);
        } else d[i] = -1;
    }
    int pos[4];
#pragma unroll
    for (int i = 0; i < 4; i++)
        if (d[i] >= 0) pos[i] = __ldg(offsets + d[i]) + atomicAdd(cursor + d[i], 1);
#pragma unroll
    for (int i = 0; i < 4; i++)
        if (d[i] >= 0) edges[pos[i]] = make_int2(s[i], __float_as_int(wt[i]));
}

// ---------------------------------------------------------------------------
// Gather-aggregate: warp per node.  out[n] = bias + sum w_e * sup_fp16[src_e]
// ---------------------------------------------------------------------------
template <typename OutT>
__global__ __launch_bounds__(256) void gather_kernel(
    const __half* __restrict__ sup,
    const int2* __restrict__ edges,
    const int* __restrict__ offsets, const float* __restrict__ bias,
    OutT* __restrict__ out)
{
    int n = (int)((blockIdx.x * (unsigned)blockDim.x + threadIdx.x) >> 5);
    int lane = threadIdx.x & 31;
    if (n >= NN) return;

    int beg = __ldg(offsets + n);
    int end = __ldg(offsets + n + 1);

    float4 acc = *(const float4*)(bias + lane * 4);

    for (int base = beg; base < end; base += 32) {
        int cnt = min(32, end - base);
        int2 p = make_int2(0, 0);
        if (lane < cnt) p = __ldg(edges + base + lane);

        int k = 0;
        for (; k + 8 <= cnt; k += 8) {
            const __half* r[8];
            float wgt[8];
#pragma unroll
            for (int u = 0; u < 8; u++) {
                int s = __shfl_sync(0xffffffffu, p.x, k + u);
                wgt[u] = __int_as_float(__shfl_sync(0xffffffffu, p.y, k + u));
                r[u] = sup + (size_t)s * DD + lane * 4;
            }
            uint2 v[8];
#pragma unroll
            for (int u = 0; u < 8; u++) v[u] = *(const uint2*)r[u];
#pragma unroll
            for (int u = 0; u < 8; u++) {
                float2 f0 = __half22float2(*reinterpret_cast<__half2*>(&v[u].x));
                float2 f1 = __half22float2(*reinterpret_cast<__half2*>(&v[u].y));
                acc.x += wgt[u] * f0.x;
                acc.y += wgt[u] * f0.y;
                acc.z += wgt[u] * f1.x;
                acc.w += wgt[u] * f1.y;
            }
        }
        for (; k < cnt; k++) {
            int s = __shfl_sync(0xffffffffu, p.x, k);
            float wg = __int_as_float(__shfl_sync(0xffffffffu, p.y, k));
            uint2 v = *(const uint2*)(sup + (size_t)s * DD + lane * 4);
            float2 f0 = __half22float2(*reinterpret_cast<__half2*>(&v.x));
            float2 f1 = __half22float2(*reinterpret_cast<__half2*>(&v.y));
            acc.x += wg * f0.x; acc.y += wg * f0.y;
            acc.z += wg * f1.x; acc.w += wg * f1.y;
        }
    }

    if constexpr (sizeof(OutT) == 4) {
        *(float4*)((float*)out + (size_t)n * DD + lane * 4) = acc;
    } else {
        __half2 h0 = __floats2half2_rn(acc.x, acc.y);
        __half2 h1 = __floats2half2_rn(acc.z, acc.w);
        uint2 pk;
        pk.x = *reinterpret_cast<uint*>(&h0);
        pk.y = *reinterpret_cast<uint*>(&h1);
        *(uint2*)((__half*)out + (size_t)n * DD + lane * 4) = pk;
    }
}

// ---------------------------------------------------------------------------
// kernel_launch
// ---------------------------------------------------------------------------
extern "C" void kernel_launch(void* const* d_in, const int* in_sizes, int n_in,
                              void* d_out, int out_size)
{
    const float* features = (const float*)d_in[0];
    const int*   edge_src = (const int*)d_in[1];
    const int*   edge_dst = (const int*)d_in[2];
    const float* edge_w   = (const float*)d_in[3];
    const float* W1       = (const float*)d_in[4];
    const float* b1       = (const float*)d_in[5];
    const float* W2       = (const float*)d_in[6];
    const float* b2       = (const float*)d_in[7];
    float* out = (float*)d_out;

    const int nE = in_sizes[1];

    __half* sup;  cudaGetSymbolAddress((void**)&sup, g_sup);
    __half* h;    cudaGetSymbolAddress((void**)&h, g_h);
    __half* w1t;  cudaGetSymbolAddress((void**)&w1t, g_w1t);
    __half* w2t;  cudaGetSymbolAddress((void**)&w2t, g_w2t);
    int* counts;  cudaGetSymbolAddress((void**)&counts, g_counts);
    int* offsets; cudaGetSymbolAddress((void**)&offsets, g_offsets);
    int2* edges;  cudaGetSymbolAddress((void**)&edges, g_edges);

    cudaFuncSetAttribute(hgemm_kernel<float, false>,
                         cudaFuncAttributeMaxDynamicSharedMemorySize, GEMM_SMEM);
    cudaFuncSetAttribute(hgemm_kernel<__half, true>,
                         cudaFuncAttributeMaxDynamicSharedMemorySize, GEMM_SMEM);

    const int gemm_grid = (NN + 63) / 64;
    const int edge4_grid = (nE + 1023) / 1024;
    const int node_grid = (NN + 255) / 256;
    const int gather_grid = (NN * 32 + 255) / 256;
    const int w_grid = (DD * DD + 255) / 256;

    // ---- CSR build + weight conversion ----
    zero_counts_kernel<<<node_grid, 256>>>(counts);
    convert_w_kernel<<<w_grid, 256>>>(W1, w1t);
    convert_w_kernel<<<w_grid, 256>>>(W2, w2t);
    hist_kernel<<<edge4_grid, 256>>>(edge_dst, counts, nE);
    scan_kernel<<<1, 1024>>>(counts, offsets);
    fill_kernel<<<edge4_grid, 256>>>(edge_src, edge_dst, edge_w,
                                     offsets, counts, edges, nE);

    // ---- Layer 1: sup = X@W1 (fp16), h = bias1 + gather (fp16) ----
    hgemm_kernel<float, false><<<gemm_grid, 256, GEMM_SMEM>>>(features, w1t, sup);
    gather_kernel<__half><<<gather_grid, 256>>>(sup, edges, offsets, b1, h);

    // ---- Layer 2: sup = relu(h)@W2 (fp16), out = bias2 + gather (fp32) ----
    hgemm_kernel<__half, true><<<gemm_grid, 256, GEMM_SMEM>>>(h, w2t, sup);
    gather_kernel<float><<<gather_grid, 256>>>(sup, edges, offsets, b2, out);
}